// round 1
// baseline (speedup 1.0000x reference)
#include <cuda_runtime.h>
#include <math.h>

#define NHEADS   4
#define WIN      7
#define NTOK     49            // 7*7
#define CDIM     128
#define HD       32
#define C3       384
#define QS       385           // padded row stride for qkv smem (odd -> conflict-free col access)
#define NWIN     64
#define NBLK     2048
#define NTHREADS 512

// smem layout (floats): xs[64*128] | qkv_s[49*QS] | attn_s[4*49*49]
#define XS_FLOATS    (64 * 128)
#define QKV_FLOATS   (NTOK * QS)
#define ATTN_FLOATS  (NHEADS * NTOK * NTOK)
#define SMEM_FLOATS  (XS_FLOATS + QKV_FLOATS + ATTN_FLOATS)
#define SMEM_BYTES   (SMEM_FLOATS * sizeof(float))

__device__ float g_bias[NHEADS * NTOK * NTOK];   // [h][i][j]

// Precompute relative-position bias table gather: bias[h][i][j] = rel_table[idx(i,j)][h]
__global__ void swin_bias_kernel(const float* __restrict__ rel_table) {
    int e = blockIdx.x * blockDim.x + threadIdx.x;
    if (e >= NHEADS * NTOK * NTOK) return;
    int h   = e / (NTOK * NTOK);
    int rem = e % (NTOK * NTOK);
    int i = rem / NTOK, j = rem % NTOK;
    int yi = i / WIN, xi = i % WIN, yj = j / WIN, xj = j % WIN;
    int r = (yi - yj + WIN - 1) * (2 * WIN - 1) + (xi - xj + WIN - 1);
    g_bias[e] = rel_table[r * NHEADS + h];
}

__global__ __launch_bounds__(NTHREADS, 1)
void swin_attn_kernel(const float* __restrict__ x_g,
                      const float* __restrict__ mask_g,
                      const float* __restrict__ qkv_w,
                      const float* __restrict__ qkv_b,
                      const float* __restrict__ proj_w,
                      const float* __restrict__ proj_b,
                      float* __restrict__ out_g) {
    const int blk  = blockIdx.x;        // window id in [0, 2048)
    const int wi   = blk & (NWIN - 1);  // mask window index (B*nW layout, nW fastest)
    const int tid  = threadIdx.x;
    const int lane = tid & 31;
    const int warp = tid >> 5;          // 0..15

    extern __shared__ float smem[];
    float* xs     = smem;                         // [64][128] (rows >=49 scratch/garbage)
    float* qkv_s  = smem + XS_FLOATS;             // [49][QS], cols: q 0..127 | k 128..255 | v 256..383
    float* attn_s = qkv_s + QKV_FLOATS;           // [4][49][49]

    // ---- stage 1: load x window [49][128] ----
    {
        const float4* xin = reinterpret_cast<const float4*>(x_g + (size_t)blk * (NTOK * CDIM));
        float4* xsv = reinterpret_cast<float4*>(xs);
        for (int o = tid; o < (NTOK * CDIM) / 4; o += NTHREADS) xsv[o] = xin[o];
    }
    __syncthreads();

    // ---- stage 2: qkv = x @ qkv_w + qkv_b  (49 x 384, K=128) ----
    {
        float acc[4][12];
        #pragma unroll
        for (int ri = 0; ri < 4; ri++)
            #pragma unroll
            for (int ci = 0; ci < 12; ci++) acc[ri][ci] = 0.f;

        const int r0 = warp;   // rows r0 + 16*ri  (up to 63; xs padded to 64 rows)
        const int c0 = lane;   // cols c0 + 32*ci

        #pragma unroll 4
        for (int k = 0; k < CDIM; k++) {
            float a[4];
            #pragma unroll
            for (int ri = 0; ri < 4; ri++) a[ri] = xs[(r0 + 16 * ri) * CDIM + k];
            #pragma unroll
            for (int ci = 0; ci < 12; ci++) {
                float b = __ldg(&qkv_w[k * C3 + c0 + 32 * ci]);
                #pragma unroll
                for (int ri = 0; ri < 4; ri++) acc[ri][ci] = fmaf(a[ri], b, acc[ri][ci]);
            }
        }
        #pragma unroll
        for (int ci = 0; ci < 12; ci++) {
            int c = c0 + 32 * ci;
            float bb = __ldg(&qkv_b[c]);
            #pragma unroll
            for (int ri = 0; ri < 4; ri++) {
                int r = r0 + 16 * ri;
                if (r < NTOK) qkv_s[r * QS + c] = acc[ri][ci] + bb;
            }
        }
    }
    __syncthreads();

    // ---- stage 3+4: logits + bias + mask, softmax -> attn_s ----
    {
        const float scale = 0.17677669529663687f;   // 1/sqrt(32)
        const float* mask_w = mask_g + (size_t)wi * NTOK * NTOK;
        for (int p = warp; p < NHEADS * NTOK; p += 16) {
            int h = p / NTOK, i = p % NTOK;
            const float* qrow = &qkv_s[i * QS + h * HD];
            int j1 = lane;
            int j2 = lane + 32;
            int j2c = (j2 < NTOK) ? j2 : (NTOK - 1);
            bool v2 = (j2 < NTOK);
            const float* k1 = &qkv_s[j1 * QS + CDIM + h * HD];
            const float* k2 = &qkv_s[j2c * QS + CDIM + h * HD];
            float s1 = 0.f, s2 = 0.f;
            #pragma unroll
            for (int d = 0; d < HD; d++) {
                float qv = qrow[d];
                s1 = fmaf(qv, k1[d], s1);
                s2 = fmaf(qv, k2[d], s2);
            }
            s1 = s1 * scale + g_bias[p * NTOK + j1] + mask_w[i * NTOK + j1];
            float s2f = s2 * scale + g_bias[p * NTOK + j2c] + mask_w[i * NTOK + j2c];
            s2 = v2 ? s2f : -INFINITY;

            float m = fmaxf(s1, s2);
            #pragma unroll
            for (int off = 16; off; off >>= 1) m = fmaxf(m, __shfl_xor_sync(0xffffffffu, m, off));
            float e1 = __expf(s1 - m);
            float e2 = v2 ? __expf(s2 - m) : 0.f;
            float sum = e1 + e2;
            #pragma unroll
            for (int off = 16; off; off >>= 1) sum += __shfl_xor_sync(0xffffffffu, sum, off);
            float inv = 1.0f / sum;
            attn_s[p * NTOK + j1] = e1 * inv;
            if (v2) attn_s[p * NTOK + j2] = e2 * inv;
        }
    }
    __syncthreads();

    // ---- stage 5: O = P @ V  -> xs[49][128] (reuse) ----
    for (int o = tid; o < NTOK * CDIM; o += NTHREADS) {
        int i = o >> 7;         // token
        int c = o & 127;        // channel = h*32 + d
        int h = c >> 5;
        const float* prow = &attn_s[(h * NTOK + i) * NTOK];
        const float* vcol = &qkv_s[2 * CDIM + c];
        float acc = 0.f;
        #pragma unroll
        for (int j = 0; j < NTOK; j++) acc = fmaf(prow[j], vcol[j * QS], acc);
        xs[o] = acc;
    }
    __syncthreads();

    // ---- stage 6: out = O @ proj_w + proj_b  (49 x 128, K=128) ----
    {
        float acc[4][4];
        #pragma unroll
        for (int ri = 0; ri < 4; ri++)
            #pragma unroll
            for (int ci = 0; ci < 4; ci++) acc[ri][ci] = 0.f;

        const int r0 = warp;
        const int c0 = lane;

        #pragma unroll 4
        for (int k = 0; k < CDIM; k++) {
            float a[4];
            #pragma unroll
            for (int ri = 0; ri < 4; ri++) a[ri] = xs[(r0 + 16 * ri) * CDIM + k];
            #pragma unroll
            for (int ci = 0; ci < 4; ci++) {
                float b = __ldg(&proj_w[k * CDIM + c0 + 32 * ci]);
                #pragma unroll
                for (int ri = 0; ri < 4; ri++) acc[ri][ci] = fmaf(a[ri], b, acc[ri][ci]);
            }
        }
        float* outp = out_g + (size_t)blk * (NTOK * CDIM);
        #pragma unroll
        for (int ci = 0; ci < 4; ci++) {
            int c = c0 + 32 * ci;
            float bb = __ldg(&proj_b[c]);
            #pragma unroll
            for (int ri = 0; ri < 4; ri++) {
                int r = r0 + 16 * ri;
                if (r < NTOK) outp[r * CDIM + c] = acc[ri][ci] + bb;
            }
        }
    }
}

extern "C" void kernel_launch(void* const* d_in, const int* in_sizes, int n_in,
                              void* d_out, int out_size) {
    const float* x      = (const float*)d_in[0];   // [32,64,7,7,128]
    const float* mask   = (const float*)d_in[1];   // [64,49,49]
    const float* qkv_w  = (const float*)d_in[2];   // [128,384]
    const float* qkv_b  = (const float*)d_in[3];   // [384]
    const float* proj_w = (const float*)d_in[4];   // [128,128]
    const float* proj_b = (const float*)d_in[5];   // [128]
    const float* rel    = (const float*)d_in[6];   // [169,4]
    float* out = (float*)d_out;

    (void)in_sizes; (void)n_in; (void)out_size;

    cudaFuncSetAttribute(swin_attn_kernel,
                         cudaFuncAttributeMaxDynamicSharedMemorySize, SMEM_BYTES);

    swin_bias_kernel<<<(NHEADS * NTOK * NTOK + 255) / 256, 256>>>(rel);
    swin_attn_kernel<<<NBLK, NTHREADS, SMEM_BYTES>>>(x, mask, qkv_w, qkv_b,
                                                     proj_w, proj_b, out);
}

// round 2
// speedup vs baseline: 1.3257x; 1.3257x over previous
#include <cuda_runtime.h>
#include <math.h>

#define NHEADS   4
#define WIN      7
#define NTOK     49
#define CDIM     128
#define HD       32
#define C3       384
#define NWIN     64
#define NBLK     2048
#define NTHREADS 512
#define PSTRIDE  52          // p_s row stride

// smem (floats): xs[49*128] | q_s[49*128] | k_s[49*128] | v_s[49*128] | p_s[4*49*52]
#define XS_F   (NTOK * CDIM)
#define PS_F   (NHEADS * NTOK * PSTRIDE)
#define SMEM_FLOATS (4 * XS_F + PS_F)
#define SMEM_BYTES  (SMEM_FLOATS * sizeof(float))

// Precombined bias+mask table: comb[wi][h][i][j]
__device__ float g_comb[NWIN * NHEADS * NTOK * NTOK];

__global__ void swin_comb_kernel(const float* __restrict__ rel_table,
                                 const float* __restrict__ mask) {
    int e = blockIdx.x * blockDim.x + threadIdx.x;
    if (e >= NWIN * NHEADS * NTOK * NTOK) return;
    int j   = e % NTOK;
    int t   = e / NTOK;
    int i   = t % NTOK;
    t /= NTOK;
    int h   = t % NHEADS;
    int w   = t / NHEADS;
    int yi = i / WIN, xi = i % WIN, yj = j / WIN, xj = j % WIN;
    int r = (yi - yj + WIN - 1) * (2 * WIN - 1) + (xi - xj + WIN - 1);
    g_comb[e] = rel_table[r * NHEADS + h] + mask[(w * NTOK + i) * NTOK + j];
}

__global__ __launch_bounds__(NTHREADS, 1)
void swin_attn_kernel(const float* __restrict__ x_g,
                      const float* __restrict__ qkv_w,
                      const float* __restrict__ qkv_b,
                      const float* __restrict__ proj_w,
                      const float* __restrict__ proj_b,
                      float* __restrict__ out_g) {
    const int blk  = blockIdx.x;
    const int wi   = blk & (NWIN - 1);
    const int tid  = threadIdx.x;
    const int lane = tid & 31;
    const int warp = tid >> 5;

    extern __shared__ float smem[];
    float* xs  = smem;                 // input x, later reused for O
    float* q_s = smem + XS_F;
    float* k_s = smem + 2 * XS_F;     // swizzled
    float* v_s = smem + 3 * XS_F;     // swizzled
    float* p_s = smem + 4 * XS_F;     // [4][49][52]

    float4* xs4 = reinterpret_cast<float4*>(xs);
    float4* q4  = reinterpret_cast<float4*>(q_s);
    float4* k4  = reinterpret_cast<float4*>(k_s);
    float4* v4  = reinterpret_cast<float4*>(v_s);

    // ---- stage 1: load x window [49][128] ----
    {
        const float4* xin = reinterpret_cast<const float4*>(x_g + (size_t)blk * (NTOK * CDIM));
        for (int o = tid; o < (NTOK * CDIM) / 4; o += NTHREADS) xs4[o] = xin[o];
    }
    __syncthreads();

    // ---- stage 2: qkv = x @ qkv_w + qkv_b ----
    // 13 warps x 4 rows; thread cols: g*128 + lane*4, g=0(Q),1(K),2(V)
    if (warp < 13) {
        float acc[4][12];
        #pragma unroll
        for (int ri = 0; ri < 4; ri++)
            #pragma unroll
            for (int ci = 0; ci < 12; ci++) acc[ri][ci] = 0.f;

        const float4* xr[4];
        #pragma unroll
        for (int ri = 0; ri < 4; ri++) {
            int rr = 4 * warp + ri; if (rr > 48) rr = 48;
            xr[ri] = reinterpret_cast<const float4*>(xs + rr * CDIM);
        }
        const float4* wv = reinterpret_cast<const float4*>(qkv_w);  // [k][96] float4s

        for (int k4i = 0; k4i < 32; k4i++) {
            float a[4][4];
            #pragma unroll
            for (int ri = 0; ri < 4; ri++) *reinterpret_cast<float4*>(a[ri]) = xr[ri][k4i];
            #pragma unroll
            for (int kk = 0; kk < 4; kk++) {
                float w[12];
                const float4* wrow = wv + (size_t)(4 * k4i + kk) * 96 + lane;
                *reinterpret_cast<float4*>(&w[0]) = wrow[0];
                *reinterpret_cast<float4*>(&w[4]) = wrow[32];
                *reinterpret_cast<float4*>(&w[8]) = wrow[64];
                #pragma unroll
                for (int ci = 0; ci < 12; ci++)
                    #pragma unroll
                    for (int ri = 0; ri < 4; ri++)
                        acc[ri][ci] = fmaf(a[ri][kk], w[ci], acc[ri][ci]);
            }
        }

        float b[12];
        {
            const float4* bv = reinterpret_cast<const float4*>(qkv_b) + lane;
            *reinterpret_cast<float4*>(&b[0]) = bv[0];
            *reinterpret_cast<float4*>(&b[4]) = bv[32];
            *reinterpret_cast<float4*>(&b[8]) = bv[64];
        }
        #pragma unroll
        for (int ri = 0; ri < 4; ri++) {
            int r = 4 * warp + ri;
            if (r < NTOK) {
                float4 qv = make_float4(acc[ri][0] + b[0], acc[ri][1] + b[1],
                                        acc[ri][2] + b[2], acc[ri][3] + b[3]);
                float4 kv = make_float4(acc[ri][4] + b[4], acc[ri][5] + b[5],
                                        acc[ri][6] + b[6], acc[ri][7] + b[7]);
                float4 vv = make_float4(acc[ri][8] + b[8], acc[ri][9] + b[9],
                                        acc[ri][10] + b[10], acc[ri][11] + b[11]);
                q4[r * 32 + lane] = qv;
                k4[r * 32 + (lane ^ (r & 7))] = kv;
                v4[r * 32 + (lane ^ (r & 7))] = vv;
            }
        }
    }
    __syncthreads();

    // ---- stage 3: logits + comb, softmax -> p_s ----
    {
        const float scale = 0.17677669529663687f;   // 1/sqrt(32)
        for (int p = warp; p < NHEADS * NTOK; p += 16) {
            int h = p / NTOK, i = p - h * NTOK;
            const int j1 = lane;
            const int j2 = lane + 32;
            const int j2c = (j2 < NTOK) ? j2 : (NTOK - 1);
            const bool v2 = (j2 < NTOK);

            float4 s1v = make_float4(0.f, 0.f, 0.f, 0.f);
            float4 s2v = make_float4(0.f, 0.f, 0.f, 0.f);
            const int hb = h * 8;   // head offset in float4 units (h*32 floats)
            #pragma unroll
            for (int d4 = 0; d4 < 8; d4++) {
                float4 qv  = q4[i * 32 + hb + d4];
                float4 k1v = k4[j1 * 32 + ((hb + d4) ^ (j1 & 7))];
                float4 k2v = k4[j2c * 32 + ((hb + d4) ^ (j2c & 7))];
                s1v.x = fmaf(qv.x, k1v.x, s1v.x); s1v.y = fmaf(qv.y, k1v.y, s1v.y);
                s1v.z = fmaf(qv.z, k1v.z, s1v.z); s1v.w = fmaf(qv.w, k1v.w, s1v.w);
                s2v.x = fmaf(qv.x, k2v.x, s2v.x); s2v.y = fmaf(qv.y, k2v.y, s2v.y);
                s2v.z = fmaf(qv.z, k2v.z, s2v.z); s2v.w = fmaf(qv.w, k2v.w, s2v.w);
            }
            float s1 = (s1v.x + s1v.y) + (s1v.z + s1v.w);
            float s2 = (s2v.x + s2v.y) + (s2v.z + s2v.w);

            const float* comb = g_comb + ((size_t)((wi * NHEADS + h) * NTOK + i)) * NTOK;
            s1 = fmaf(s1, scale, comb[j1]);
            float s2f = fmaf(s2, scale, comb[j2c]);
            s2 = v2 ? s2f : -INFINITY;

            float m = fmaxf(s1, s2);
            #pragma unroll
            for (int off = 16; off; off >>= 1) m = fmaxf(m, __shfl_xor_sync(0xffffffffu, m, off));
            float e1 = __expf(s1 - m);
            float e2 = v2 ? __expf(s2 - m) : 0.f;
            float sum = e1 + e2;
            #pragma unroll
            for (int off = 16; off; off >>= 1) sum += __shfl_xor_sync(0xffffffffu, sum, off);
            float inv = 1.0f / sum;

            float* prow = p_s + (h * NTOK + i) * PSTRIDE;
            prow[j1] = e1 * inv;
            if (v2) prow[j2] = e2 * inv;
        }
    }
    __syncthreads();

    // ---- stage 5: O = P @ V -> xs (one warp per token i; lane owns float4 of channels) ----
    {
        const int h = lane >> 3;    // head of this lane's 4 channels
        for (int i = warp; i < NTOK; i += 16) {
            const float* prow = p_s + (h * NTOK + i) * PSTRIDE;
            float4 acc = make_float4(0.f, 0.f, 0.f, 0.f);
            #pragma unroll 7
            for (int j = 0; j < NTOK; j++) {
                float pj = prow[j];
                float4 vv = v4[j * 32 + (lane ^ (j & 7))];
                acc.x = fmaf(pj, vv.x, acc.x); acc.y = fmaf(pj, vv.y, acc.y);
                acc.z = fmaf(pj, vv.z, acc.z); acc.w = fmaf(pj, vv.w, acc.w);
            }
            xs4[i * 32 + lane] = acc;
        }
    }
    __syncthreads();

    // ---- stage 6: out = O @ proj_w + proj_b ----
    if (warp < 13) {
        float acc[4][4];
        #pragma unroll
        for (int ri = 0; ri < 4; ri++)
            #pragma unroll
            for (int ci = 0; ci < 4; ci++) acc[ri][ci] = 0.f;

        const float4* xr[4];
        #pragma unroll
        for (int ri = 0; ri < 4; ri++) {
            int rr = 4 * warp + ri; if (rr > 48) rr = 48;
            xr[ri] = reinterpret_cast<const float4*>(xs + rr * CDIM);
        }
        const float4* wv = reinterpret_cast<const float4*>(proj_w);  // [k][32] float4s

        for (int k4i = 0; k4i < 32; k4i++) {
            float a[4][4];
            #pragma unroll
            for (int ri = 0; ri < 4; ri++) *reinterpret_cast<float4*>(a[ri]) = xr[ri][k4i];
            #pragma unroll
            for (int kk = 0; kk < 4; kk++) {
                float w[4];
                *reinterpret_cast<float4*>(w) = wv[(size_t)(4 * k4i + kk) * 32 + lane];
                #pragma unroll
                for (int ci = 0; ci < 4; ci++)
                    #pragma unroll
                    for (int ri = 0; ri < 4; ri++)
                        acc[ri][ci] = fmaf(a[ri][kk], w[ci], acc[ri][ci]);
            }
        }

        float b[4];
        *reinterpret_cast<float4*>(b) = reinterpret_cast<const float4*>(proj_b)[lane];
        float4* outp = reinterpret_cast<float4*>(out_g + (size_t)blk * (NTOK * CDIM));
        #pragma unroll
        for (int ri = 0; ri < 4; ri++) {
            int r = 4 * warp + ri;
            if (r < NTOK) {
                outp[r * 32 + lane] = make_float4(acc[ri][0] + b[0], acc[ri][1] + b[1],
                                                  acc[ri][2] + b[2], acc[ri][3] + b[3]);
            }
        }
    }
}

extern "C" void kernel_launch(void* const* d_in, const int* in_sizes, int n_in,
                              void* d_out, int out_size) {
    const float* x      = (const float*)d_in[0];
    const float* mask   = (const float*)d_in[1];
    const float* qkv_w  = (const float*)d_in[2];
    const float* qkv_b  = (const float*)d_in[3];
    const float* proj_w = (const float*)d_in[4];
    const float* proj_b = (const float*)d_in[5];
    const float* rel    = (const float*)d_in[6];
    float* out = (float*)d_out;

    (void)in_sizes; (void)n_in; (void)out_size;

    cudaFuncSetAttribute(swin_attn_kernel,
                         cudaFuncAttributeMaxDynamicSharedMemorySize, SMEM_BYTES);

    int ncomb = NWIN * NHEADS * NTOK * NTOK;
    swin_comb_kernel<<<(ncomb + 255) / 256, 256>>>(rel, mask);
    swin_attn_kernel<<<NBLK, NTHREADS, SMEM_BYTES>>>(x, qkv_w, qkv_b,
                                                     proj_w, proj_b, out);
}

// round 3
// speedup vs baseline: 1.8903x; 1.4260x over previous
#include <cuda_runtime.h>
#include <math.h>

#define NHEADS   4
#define WIN      7
#define NTOK     49
#define CDIM     128
#define C3       384
#define NWIN     64
#define NBLK     2048
#define NTHREADS 512
#define PSTRIDE  52

typedef unsigned long long u64;

// packed fp32 helpers (sm_100a f32x2)
__device__ __forceinline__ void ffma2(u64 &d, u64 a, u64 b) {
    asm("fma.rn.f32x2 %0, %1, %2, %3;" : "=l"(d) : "l"(a), "l"(b), "l"(d));
}
__device__ __forceinline__ u64 dup2(float x) {
    u64 r; asm("mov.b64 %0, {%1, %1};" : "=l"(r) : "f"(x)); return r;
}
__device__ __forceinline__ float2 unpack2(u64 v) {
    float2 r; asm("mov.b64 {%0, %1}, %2;" : "=f"(r.x), "=f"(r.y) : "l"(v)); return r;
}

// smem (floats): xs[49*128] | q_s[49*128] | k_s[49*128] | v_s[52*128] | p_s[4*49*52]
#define XS_F   (NTOK * CDIM)           // 6272
#define V_F    (52 * CDIM)             // 6656 (rows 49..51 zero)
#define PS_F   (NHEADS * NTOK * PSTRIDE)
#define SMEM_FLOATS (3 * XS_F + V_F + PS_F)
#define SMEM_BYTES  (SMEM_FLOATS * sizeof(float))

__device__ float g_comb[NWIN * NHEADS * NTOK * NTOK];   // bias + mask precombined

__global__ void swin_comb_kernel(const float* __restrict__ rel_table,
                                 const float* __restrict__ mask) {
    int e = blockIdx.x * blockDim.x + threadIdx.x;
    if (e >= NWIN * NHEADS * NTOK * NTOK) return;
    int j = e % NTOK;
    int t = e / NTOK;
    int i = t % NTOK;  t /= NTOK;
    int h = t % NHEADS;
    int w = t / NHEADS;
    int yi = i / WIN, xi = i % WIN, yj = j / WIN, xj = j % WIN;
    int r = (yi - yj + WIN - 1) * (2 * WIN - 1) + (xi - xj + WIN - 1);
    g_comb[e] = rel_table[r * NHEADS + h] + mask[(w * NTOK + i) * NTOK + j];
}

__global__ __launch_bounds__(NTHREADS, 1)
void swin_attn_kernel(const float* __restrict__ x_g,
                      const float* __restrict__ qkv_w,
                      const float* __restrict__ qkv_b,
                      const float* __restrict__ proj_w,
                      const float* __restrict__ proj_b,
                      float* __restrict__ out_g) {
    const int blk  = blockIdx.x;
    const int wi   = blk & (NWIN - 1);
    const int tid  = threadIdx.x;
    const int lane = tid & 31;
    const int warp = tid >> 5;

    extern __shared__ float smem[];
    float* xs  = smem;                       // x, later O
    float* q_s = smem + XS_F;
    float* k_s = smem + 2 * XS_F;            // swizzled
    float* v_s = smem + 3 * XS_F;            // swizzled, 52 rows
    float* p_s = smem + 3 * XS_F + V_F;      // [4][49][52], cols 49..51 zero

    float4* xs4 = reinterpret_cast<float4*>(xs);
    float4* q4  = reinterpret_cast<float4*>(q_s);
    float4* k4  = reinterpret_cast<float4*>(k_s);
    float4* v4  = reinterpret_cast<float4*>(v_s);

    // ---- stage 1: load x + zero-fill padding ----
    {
        const float4* xin = reinterpret_cast<const float4*>(x_g + (size_t)blk * (NTOK * CDIM));
        for (int o = tid; o < (NTOK * CDIM) / 4; o += NTHREADS) xs4[o] = xin[o];
        if (tid < 96) v4[49 * 32 + tid] = make_float4(0.f, 0.f, 0.f, 0.f);  // V rows 49..51
        for (int o = tid; o < NHEADS * NTOK * 3; o += NTHREADS) {           // P cols 49..51
            int rr = o / 3, cc = o % 3;
            p_s[rr * PSTRIDE + 49 + cc] = 0.f;
        }
    }
    __syncthreads();

    // ---- stage 2: qkv = x @ qkv_w + qkv_b (12 warps: 3 colgroups x 4 rowgroups) ----
    if (warp < 12) {
        const int g  = warp >> 2;            // 0=Q 1=K 2=V
        const int rg = warp & 3;
        const int rbase = rg * 13;
        int rr[13];
        #pragma unroll
        for (int t = 0; t < 13; t++) { int r = rbase + t; rr[t] = (r > 48) ? 48 : r; }

        u64 acc[13][2];
        #pragma unroll
        for (int t = 0; t < 13; t++) { acc[t][0] = 0ull; acc[t][1] = 0ull; }

        const float4* wv = reinterpret_cast<const float4*>(qkv_w) + g * 32 + lane;  // row stride 96

        #pragma unroll 2
        for (int k4i = 0; k4i < 32; k4i++) {
            float4 w4[4];
            #pragma unroll
            for (int kk = 0; kk < 4; kk++) w4[kk] = wv[(size_t)(4 * k4i + kk) * 96];
            #pragma unroll
            for (int t = 0; t < 13; t++) {
                float4 a4 = xs4[rr[t] * 32 + k4i];     // broadcast
                float av[4] = {a4.x, a4.y, a4.z, a4.w};
                #pragma unroll
                for (int kk = 0; kk < 4; kk++) {
                    u64 ad = dup2(av[kk]);
                    const u64* wp = reinterpret_cast<const u64*>(&w4[kk]);
                    ffma2(acc[t][0], ad, wp[0]);
                    ffma2(acc[t][1], ad, wp[1]);
                }
            }
        }

        float4 b4 = reinterpret_cast<const float4*>(qkv_b)[g * 32 + lane];
        #pragma unroll
        for (int t = 0; t < 13; t++) {
            int r = rbase + t;
            if (r < NTOK) {
                float2 p0 = unpack2(acc[t][0]);
                float2 p1 = unpack2(acc[t][1]);
                float4 o = make_float4(p0.x + b4.x, p0.y + b4.y, p1.x + b4.z, p1.y + b4.w);
                if (g == 0)      q4[r * 32 + lane] = o;
                else if (g == 1) k4[r * 32 + (lane ^ (r & 7))] = o;
                else             v4[r * 32 + (lane ^ (r & 7))] = o;
            }
        }
    }
    __syncthreads();

    // ---- stage 3: logits (d-pair packed) + softmax -> p_s ----
    {
        const float scale = 0.17677669529663687f;   // 1/sqrt(32)
        const int j1 = lane;
        const int j2 = lane + 32;
        const int j2c = (j2 < NTOK) ? j2 : (NTOK - 1);
        const bool vld2 = (j2 < NTOK);

        for (int grp = warp; grp < 28; grp += 16) {
            const int h  = grp / 7;
            const int i0 = (grp % 7) * 8;
            const int hb = h * 8;
            int ir[8];
            #pragma unroll
            for (int ii = 0; ii < 8; ii++) { int i = i0 + ii; ir[ii] = (i > 48) ? 48 : i; }

            u64 acc[8][2];
            #pragma unroll
            for (int ii = 0; ii < 8; ii++) { acc[ii][0] = 0ull; acc[ii][1] = 0ull; }

            #pragma unroll
            for (int d4 = 0; d4 < 8; d4++) {
                float4 k1v = k4[j1  * 32 + ((hb + d4) ^ (j1  & 7))];
                float4 k2v = k4[j2c * 32 + ((hb + d4) ^ (j2c & 7))];
                const u64* k1p = reinterpret_cast<const u64*>(&k1v);
                const u64* k2p = reinterpret_cast<const u64*>(&k2v);
                #pragma unroll
                for (int ii = 0; ii < 8; ii++) {
                    float4 qv = q4[ir[ii] * 32 + hb + d4];   // broadcast
                    const u64* qp = reinterpret_cast<const u64*>(&qv);
                    ffma2(acc[ii][0], qp[0], k1p[0]);
                    ffma2(acc[ii][0], qp[1], k1p[1]);
                    ffma2(acc[ii][1], qp[0], k2p[0]);
                    ffma2(acc[ii][1], qp[1], k2p[1]);
                }
            }

            #pragma unroll
            for (int ii = 0; ii < 8; ii++) {
                int i = i0 + ii;
                bool iv = (i < NTOK);
                int ic = iv ? i : 48;
                float2 a0 = unpack2(acc[ii][0]);
                float2 a1 = unpack2(acc[ii][1]);
                float s1 = a0.x + a0.y;
                float s2 = a1.x + a1.y;
                const float* comb = g_comb + ((size_t)((wi * NHEADS + h) * NTOK + ic)) * NTOK;
                s1 = fmaf(s1, scale, comb[j1]);
                float s2f = fmaf(s2, scale, comb[j2c]);
                s2 = vld2 ? s2f : -INFINITY;

                float m = fmaxf(s1, s2);
                #pragma unroll
                for (int off = 16; off; off >>= 1) m = fmaxf(m, __shfl_xor_sync(0xffffffffu, m, off));
                float e1 = __expf(s1 - m);
                float e2 = vld2 ? __expf(s2 - m) : 0.f;
                float sum = e1 + e2;
                #pragma unroll
                for (int off = 16; off; off >>= 1) sum += __shfl_xor_sync(0xffffffffu, sum, off);
                float inv = 1.0f / sum;

                if (iv) {
                    float* prow = p_s + (h * NTOK + i) * PSTRIDE;
                    prow[j1] = e1 * inv;
                    if (vld2) prow[j2] = e2 * inv;
                }
            }
        }
    }
    __syncthreads();

    // ---- stage 5: O = P @ V (13 warps x 4 tokens, channel-pair packed) -> xs ----
    if (warp < 13) {
        const int h  = lane >> 3;            // head of this lane's channels
        const int i0 = warp * 4;
        int ir[4];
        #pragma unroll
        for (int ii = 0; ii < 4; ii++) { int i = i0 + ii; ir[ii] = (i > 48) ? 48 : i; }

        u64 acc[4][2];
        #pragma unroll
        for (int ii = 0; ii < 4; ii++) { acc[ii][0] = 0ull; acc[ii][1] = 0ull; }

        #pragma unroll 4
        for (int j4 = 0; j4 < 13; j4++) {
            float4 pv[4];
            #pragma unroll
            for (int ii = 0; ii < 4; ii++)
                pv[ii] = reinterpret_cast<const float4*>(p_s + (h * NTOK + ir[ii]) * PSTRIDE)[j4];
            #pragma unroll
            for (int jj = 0; jj < 4; jj++) {
                int j = j4 * 4 + jj;
                float4 vv = v4[j * 32 + (lane ^ (j & 7))];
                const u64* vp = reinterpret_cast<const u64*>(&vv);
                const float pj0 = (&pv[0].x)[jj];
                const float pj1 = (&pv[1].x)[jj];
                const float pj2 = (&pv[2].x)[jj];
                const float pj3 = (&pv[3].x)[jj];
                u64 d0 = dup2(pj0), d1 = dup2(pj1), d2 = dup2(pj2), d3 = dup2(pj3);
                ffma2(acc[0][0], d0, vp[0]); ffma2(acc[0][1], d0, vp[1]);
                ffma2(acc[1][0], d1, vp[0]); ffma2(acc[1][1], d1, vp[1]);
                ffma2(acc[2][0], d2, vp[0]); ffma2(acc[2][1], d2, vp[1]);
                ffma2(acc[3][0], d3, vp[0]); ffma2(acc[3][1], d3, vp[1]);
            }
        }

        #pragma unroll
        for (int ii = 0; ii < 4; ii++) {
            int i = i0 + ii;
            if (i < NTOK) {
                float2 p0 = unpack2(acc[ii][0]);
                float2 p1 = unpack2(acc[ii][1]);
                xs4[i * 32 + lane] = make_float4(p0.x, p0.y, p1.x, p1.y);
            }
        }
    }
    __syncthreads();

    // ---- stage 6: out = O @ proj_w + proj_b (8 warps x 7 rows) ----
    if (warp < 8) {
        const int rbase = warp * 7;
        int rr[7];
        #pragma unroll
        for (int t = 0; t < 7; t++) { int r = rbase + t; rr[t] = (r > 48) ? 48 : r; }

        u64 acc[7][2];
        #pragma unroll
        for (int t = 0; t < 7; t++) { acc[t][0] = 0ull; acc[t][1] = 0ull; }

        const float4* wv = reinterpret_cast<const float4*>(proj_w) + lane;  // row stride 32

        #pragma unroll 2
        for (int k4i = 0; k4i < 32; k4i++) {
            float4 w4[4];
            #pragma unroll
            for (int kk = 0; kk < 4; kk++) w4[kk] = wv[(size_t)(4 * k4i + kk) * 32];
            #pragma unroll
            for (int t = 0; t < 7; t++) {
                float4 a4 = xs4[rr[t] * 32 + k4i];
                float av[4] = {a4.x, a4.y, a4.z, a4.w};
                #pragma unroll
                for (int kk = 0; kk < 4; kk++) {
                    u64 ad = dup2(av[kk]);
                    const u64* wp = reinterpret_cast<const u64*>(&w4[kk]);
                    ffma2(acc[t][0], ad, wp[0]);
                    ffma2(acc[t][1], ad, wp[1]);
                }
            }
        }

        float4 b4 = reinterpret_cast<const float4*>(proj_b)[lane];
        float4* outp = reinterpret_cast<float4*>(out_g + (size_t)blk * (NTOK * CDIM));
        #pragma unroll
        for (int t = 0; t < 7; t++) {
            int r = rbase + t;
            if (r < NTOK) {
                float2 p0 = unpack2(acc[t][0]);
                float2 p1 = unpack2(acc[t][1]);
                outp[r * 32 + lane] = make_float4(p0.x + b4.x, p0.y + b4.y,
                                                  p1.x + b4.z, p1.y + b4.w);
            }
        }
    }
}

extern "C" void kernel_launch(void* const* d_in, const int* in_sizes, int n_in,
                              void* d_out, int out_size) {
    const float* x      = (const float*)d_in[0];
    const float* mask   = (const float*)d_in[1];
    const float* qkv_w  = (const float*)d_in[2];
    const float* qkv_b  = (const float*)d_in[3];
    const float* proj_w = (const float*)d_in[4];
    const float* proj_b = (const float*)d_in[5];
    const float* rel    = (const float*)d_in[6];
    float* out = (float*)d_out;

    (void)in_sizes; (void)n_in; (void)out_size;

    cudaFuncSetAttribute(swin_attn_kernel,
                         cudaFuncAttributeMaxDynamicSharedMemorySize, SMEM_BYTES);

    int ncomb = NWIN * NHEADS * NTOK * NTOK;
    swin_comb_kernel<<<(ncomb + 255) / 256, 256>>>(rel, mask);
    swin_attn_kernel<<<NBLK, NTHREADS, SMEM_BYTES>>>(x, qkv_w, qkv_b,
                                                     proj_w, proj_b, out);
}